// round 10
// baseline (speedup 1.0000x reference)
#include <cuda_runtime.h>
#include <math.h>

#define MAX_M 50000
#define MAX_B 5000
#define DD    256
#define DQ    64        // DD/4 float4 per row
#define KK    100

// Scratch (device globals; no allocation allowed)
__device__ float4 g_men_emb[(size_t)MAX_M * DQ];   // 51.2 MB
__device__ float  g_sel[MAX_M];
__device__ int    g_type_idx[MAX_B];

__device__ __forceinline__ float4 f4add(float4 a, float4 b) {
    return make_float4(a.x + b.x, a.y + b.y, a.z + b.z, a.w + b.w);
}
__device__ __forceinline__ float4 f4fma(float s, float4 a, float4 acc) {
    return make_float4(fmaf(s, a.x, acc.x), fmaf(s, a.y, acc.y),
                       fmaf(s, a.z, acc.z), fmaf(s, a.w, acc.w));
}
__device__ __forceinline__ float f4dot(float4 a, float4 b) {
    return a.x * b.x + a.y * b.y + a.z * b.z + a.w * b.w;
}
__device__ __forceinline__ float4 f4scale(float4 a, float s) {
    return make_float4(a.x * s, a.y * s, a.z * s, a.w * s);
}

// ---------------------------------------------------------------------------
// Kernel 0: warp-per-bag argmax over typeTensor[B, K] (first-max semantics)
// ---------------------------------------------------------------------------
__global__ void type_argmax_kernel(const float* __restrict__ typeT, int B) {
    int gwarp = (blockIdx.x * blockDim.x + threadIdx.x) >> 5;
    int lane  = threadIdx.x & 31;
    if (gwarp >= B) return;
    const float* row = typeT + (size_t)gwarp * KK;

    float best = -INFINITY;
    int   bi   = 0x7FFFFFFF;
    for (int k = lane; k < KK; k += 32) {
        float v = row[k];
        if (v > best || (v == best && k < bi)) { best = v; bi = k; }
    }
    #pragma unroll
    for (int o = 16; o; o >>= 1) {
        float ov = __shfl_xor_sync(0xFFFFFFFFu, best, o);
        int   oi = __shfl_xor_sync(0xFFFFFFFFu, bi,   o);
        if (ov > best || (ov == best && oi < bi)) { best = ov; bi = oi; }
    }
    if (lane == 0) g_type_idx[gwarp] = bi;
}

// ---------------------------------------------------------------------------
// Kernel 1: warp-per-mention mean embedding + selected-column score.
//   EXACT measured-80us config: (256,6), 2-token unroll, 4 LDG.128 in flight.
// ---------------------------------------------------------------------------
__global__ __launch_bounds__(256, 6)
void mention_kernel(const int* __restrict__ feat,
                    const int* __restrict__ off,
                    const int* __restrict__ scope,
                    const float4* __restrict__ embv,   // [V][64]
                    const float4* __restrict__ Wv,     // [K][64]
                    int T, int M, int B) {
    int warp = threadIdx.x >> 5;
    int lane = threadIdx.x & 31;
    int m = blockIdx.x * 8 + warp;
    if (m >= M) return;

    // bag id + selected column (lane 0 searches, broadcast)
    int col = 0;
    if (lane == 0) {
        int lo = 0, hi = B;
        while (hi - lo > 1) {
            int mid = (lo + hi) >> 1;
            if (scope[mid] <= m) lo = mid; else hi = mid;
        }
        col = g_type_idx[lo];
    }
    col = __shfl_sync(0xFFFFFFFFu, col, 0);

    int start = off[m];
    int end   = (m + 1 < M) ? off[m + 1] : T;

    float4 s0 = make_float4(0.f, 0.f, 0.f, 0.f);
    float4 s1 = make_float4(0.f, 0.f, 0.f, 0.f);

    int t = start;
    for (; t + 1 < end; t += 2) {
        int f0 = __ldg(&feat[t]);
        int f1 = __ldg(&feat[t + 1]);
        const float4* r0 = embv + (size_t)f0 * DQ;
        const float4* r1 = embv + (size_t)f1 * DQ;
        float4 x0 = __ldg(&r0[lane]);
        float4 x1 = __ldg(&r0[lane + 32]);
        float4 y0 = __ldg(&r1[lane]);
        float4 y1 = __ldg(&r1[lane + 32]);
        s0 = f4add(s0, f4add(x0, y0));
        s1 = f4add(s1, f4add(x1, y1));
    }
    if (t < end) {
        int f0 = __ldg(&feat[t]);
        const float4* r0 = embv + (size_t)f0 * DQ;
        s0 = f4add(s0, __ldg(&r0[lane]));
        s1 = f4add(s1, __ldg(&r0[lane + 32]));
    }

    float inv = 1.0f / (float)(end - start);
    s0 = f4scale(s0, inv);
    s1 = f4scale(s1, inv);

    // streaming stores: don't evict the L2-resident embedding table
    __stcs(&g_men_emb[(size_t)m * DQ + lane],      s0);
    __stcs(&g_men_emb[(size_t)m * DQ + 32 + lane], s1);

    // selected-column score
    float4 w0 = __ldg(&Wv[(size_t)col * DQ + lane]);
    float4 w1 = __ldg(&Wv[(size_t)col * DQ + 32 + lane]);
    float dot = f4dot(s0, w0) + f4dot(s1, w1);
    #pragma unroll
    for (int o = 16; o; o >>= 1) dot += __shfl_xor_sync(0xFFFFFFFFu, dot, o);
    if (lane == 0) g_sel[m] = dot;
}

// ---------------------------------------------------------------------------
// Kernel 2: fully fused bag stage. 8 warps/block = 8 bags.
//   Phase A (per warp, measured 20.9us standalone): segment softmax over
//   g_sel + attention-weighted accumulate of men_emb -> bag vector in regs.
//   Phase B: bag vectors to smem; each warp computes its bag's 100 output
//   dots (lanes = k strided by 32; bagv smem reads are warp-broadcast,
//   W rows are L1-resident after first touch).
// ---------------------------------------------------------------------------
__global__ __launch_bounds__(256, 4)
void bag_fused_kernel(const int* __restrict__ scope,
                      const float4* __restrict__ Wv,   // [K][64]
                      float* __restrict__ out,
                      int B) {
    __shared__ float4 bagv_sm[8][DQ];   // 8 KB

    int warp  = threadIdx.x >> 5;
    int lane  = threadIdx.x & 31;
    int b     = blockIdx.x * 8 + warp;
    bool live = (b < B);

    float4 acc0 = make_float4(0.f, 0.f, 0.f, 0.f);
    float4 acc1 = make_float4(0.f, 0.f, 0.f, 0.f);

    if (live) {
        int s0 = scope[b], s1 = scope[b + 1];

        // segment-stable softmax constants
        float mx = -INFINITY;
        for (int m = s0 + lane; m < s1; m += 32) mx = fmaxf(mx, g_sel[m]);
        #pragma unroll
        for (int o = 16; o; o >>= 1) mx = fmaxf(mx, __shfl_xor_sync(0xFFFFFFFFu, mx, o));
        float sum = 0.f;
        for (int m = s0 + lane; m < s1; m += 32) sum += expf(g_sel[m] - mx);
        #pragma unroll
        for (int o = 16; o; o >>= 1) sum += __shfl_xor_sync(0xFFFFFFFFu, sum, o);
        float inv = 1.0f / sum;

        int m = s0;
        for (; m + 1 < s1; m += 2) {
            float a0 = expf(g_sel[m]     - mx) * inv;
            float a1 = expf(g_sel[m + 1] - mx) * inv;
            float4 v00 = __ldcs(&g_men_emb[(size_t)m * DQ + lane]);
            float4 v01 = __ldcs(&g_men_emb[(size_t)m * DQ + 32 + lane]);
            float4 v10 = __ldcs(&g_men_emb[(size_t)(m + 1) * DQ + lane]);
            float4 v11 = __ldcs(&g_men_emb[(size_t)(m + 1) * DQ + 32 + lane]);
            acc0 = f4fma(a0, v00, acc0);
            acc1 = f4fma(a0, v01, acc1);
            acc0 = f4fma(a1, v10, acc0);
            acc1 = f4fma(a1, v11, acc1);
        }
        if (m < s1) {
            float a0 = expf(g_sel[m] - mx) * inv;
            float4 v00 = __ldcs(&g_men_emb[(size_t)m * DQ + lane]);
            float4 v01 = __ldcs(&g_men_emb[(size_t)m * DQ + 32 + lane]);
            acc0 = f4fma(a0, v00, acc0);
            acc1 = f4fma(a0, v01, acc1);
        }
    }

    bagv_sm[warp][lane]      = acc0;
    bagv_sm[warp][lane + 32] = acc1;
    __syncthreads();

    if (live) {
        const float4* bagv = bagv_sm[warp];
        for (int k = lane; k < KK; k += 32) {
            const float4* wrow = Wv + (size_t)k * DQ;
            float dot = 0.f;
            #pragma unroll 8
            for (int j = 0; j < DQ; ++j)
                dot += f4dot(bagv[j], __ldg(&wrow[j]));
            out[(size_t)b * KK + k] = dot;
        }
    }
}

// ---------------------------------------------------------------------------
extern "C" void kernel_launch(void* const* d_in, const int* in_sizes, int n_in,
                              void* d_out, int out_size) {
    const int*    feat  = (const int*)d_in[0];    // feature_seq [T]
    const int*    off   = (const int*)d_in[1];    // offset_seq  [M]
    const int*    scope = (const int*)d_in[2];    // scope       [B+1]
    const float*  typeT = (const float*)d_in[3];  // typeTensor  [B,K]
    const float4* embv  = (const float4*)d_in[4]; // word_embedding [V,D]
    const float4* Wv    = (const float4*)d_in[5]; // linear_weight  [K,D]
    float* out = (float*)d_out;

    int T = in_sizes[0];
    int M = in_sizes[1];
    int B = in_sizes[2] - 1;

    type_argmax_kernel<<<(B * 32 + 255) / 256, 256>>>(typeT, B);
    mention_kernel<<<(M + 7) / 8, 256>>>(feat, off, scope, embv, Wv, T, M, B);
    bag_fused_kernel<<<(B + 7) / 8, 256>>>(scope, Wv, out, B);
}

// round 11
// speedup vs baseline: 1.8479x; 1.8479x over previous
#include <cuda_runtime.h>
#include <math.h>

#define MAX_M 50000
#define MAX_B 5000
#define DD    256
#define DQ    64        // DD/4 float4 per row
#define KK    100
#define KQ    25        // KK/4 float4 per output row

// Scratch (device globals; no allocation allowed)
__device__ float4 g_men_emb[(size_t)MAX_M * DQ];   // 51.2 MB
__device__ float4 g_bag_emb[(size_t)MAX_B * DQ];   // 5.1 MB
__device__ float  g_sel[MAX_M];
__device__ int    g_type_idx[MAX_B];
__device__ float  g_Wt[DD * KK];                   // W transposed [D][K], k contiguous

__device__ __forceinline__ float4 f4add(float4 a, float4 b) {
    return make_float4(a.x + b.x, a.y + b.y, a.z + b.z, a.w + b.w);
}
__device__ __forceinline__ float4 f4fma(float s, float4 a, float4 acc) {
    return make_float4(fmaf(s, a.x, acc.x), fmaf(s, a.y, acc.y),
                       fmaf(s, a.z, acc.z), fmaf(s, a.w, acc.w));
}
__device__ __forceinline__ float f4dot(float4 a, float4 b) {
    return a.x * b.x + a.y * b.y + a.z * b.z + a.w * b.w;
}
__device__ __forceinline__ float4 f4scale(float4 a, float s) {
    return make_float4(a.x * s, a.y * s, a.z * s, a.w * s);
}

// ---------------------------------------------------------------------------
// Kernel 0: warp-per-bag argmax over typeTensor[B, K] (first-max semantics)
// ---------------------------------------------------------------------------
__global__ void type_argmax_kernel(const float* __restrict__ typeT, int B) {
    int gwarp = (blockIdx.x * blockDim.x + threadIdx.x) >> 5;
    int lane  = threadIdx.x & 31;
    if (gwarp >= B) return;
    const float* row = typeT + (size_t)gwarp * KK;

    float best = -INFINITY;
    int   bi   = 0x7FFFFFFF;
    for (int k = lane; k < KK; k += 32) {
        float v = row[k];
        if (v > best || (v == best && k < bi)) { best = v; bi = k; }
    }
    #pragma unroll
    for (int o = 16; o; o >>= 1) {
        float ov = __shfl_xor_sync(0xFFFFFFFFu, best, o);
        int   oi = __shfl_xor_sync(0xFFFFFFFFu, bi,   o);
        if (ov > best || (ov == best && oi < bi)) { best = ov; bi = oi; }
    }
    if (lane == 0) g_type_idx[gwarp] = bi;
}

// ---------------------------------------------------------------------------
// Kernel 0b: transpose W [K][D] -> g_Wt [D][K]  (k contiguous -> coalesced)
// ---------------------------------------------------------------------------
__global__ void transpose_w_kernel(const float* __restrict__ W) {
    int idx = blockIdx.x * 256 + threadIdx.x;   // idx = d*KK + k (write-coalesced)
    if (idx < KK * DD) {
        int d = idx / KK, k = idx % KK;
        g_Wt[idx] = W[(size_t)k * DD + d];
    }
}

// ---------------------------------------------------------------------------
// Kernel 1: warp-per-mention mean embedding + selected-column score.
//   EXACT measured-80us config: (256,6), 2-token unroll, 4 LDG.128 in flight.
// ---------------------------------------------------------------------------
__global__ __launch_bounds__(256, 6)
void mention_kernel(const int* __restrict__ feat,
                    const int* __restrict__ off,
                    const int* __restrict__ scope,
                    const float4* __restrict__ embv,   // [V][64]
                    const float4* __restrict__ Wv,     // [K][64]
                    int T, int M, int B) {
    int warp = threadIdx.x >> 5;
    int lane = threadIdx.x & 31;
    int m = blockIdx.x * 8 + warp;
    if (m >= M) return;

    // bag id + selected column (lane 0 searches, broadcast)
    int col = 0;
    if (lane == 0) {
        int lo = 0, hi = B;
        while (hi - lo > 1) {
            int mid = (lo + hi) >> 1;
            if (scope[mid] <= m) lo = mid; else hi = mid;
        }
        col = g_type_idx[lo];
    }
    col = __shfl_sync(0xFFFFFFFFu, col, 0);

    int start = off[m];
    int end   = (m + 1 < M) ? off[m + 1] : T;

    float4 s0 = make_float4(0.f, 0.f, 0.f, 0.f);
    float4 s1 = make_float4(0.f, 0.f, 0.f, 0.f);

    int t = start;
    for (; t + 1 < end; t += 2) {
        int f0 = __ldg(&feat[t]);
        int f1 = __ldg(&feat[t + 1]);
        const float4* r0 = embv + (size_t)f0 * DQ;
        const float4* r1 = embv + (size_t)f1 * DQ;
        float4 x0 = __ldg(&r0[lane]);
        float4 x1 = __ldg(&r0[lane + 32]);
        float4 y0 = __ldg(&r1[lane]);
        float4 y1 = __ldg(&r1[lane + 32]);
        s0 = f4add(s0, f4add(x0, y0));
        s1 = f4add(s1, f4add(x1, y1));
    }
    if (t < end) {
        int f0 = __ldg(&feat[t]);
        const float4* r0 = embv + (size_t)f0 * DQ;
        s0 = f4add(s0, __ldg(&r0[lane]));
        s1 = f4add(s1, __ldg(&r0[lane + 32]));
    }

    float inv = 1.0f / (float)(end - start);
    s0 = f4scale(s0, inv);
    s1 = f4scale(s1, inv);

    // streaming stores: don't evict the L2-resident embedding table
    __stcs(&g_men_emb[(size_t)m * DQ + lane],      s0);
    __stcs(&g_men_emb[(size_t)m * DQ + 32 + lane], s1);

    // selected-column score
    float4 w0 = __ldg(&Wv[(size_t)col * DQ + lane]);
    float4 w1 = __ldg(&Wv[(size_t)col * DQ + 32 + lane]);
    float dot = f4dot(s0, w0) + f4dot(s1, w1);
    #pragma unroll
    for (int o = 16; o; o >>= 1) dot += __shfl_xor_sync(0xFFFFFFFFu, dot, o);
    if (lane == 0) g_sel[m] = dot;
}

// ---------------------------------------------------------------------------
// Kernel 2: warp-per-bag fused softmax + attention-weighted accumulate.
//   (measured 20.9us) -> g_bag_emb
// ---------------------------------------------------------------------------
__global__ __launch_bounds__(256, 4)
void bag_acc_kernel(const int* __restrict__ scope, int B) {
    int gwarp = (blockIdx.x * blockDim.x + threadIdx.x) >> 5;
    int lane  = threadIdx.x & 31;
    if (gwarp >= B) return;

    int s0 = scope[gwarp], s1 = scope[gwarp + 1];

    // segment-stable softmax constants
    float mx = -INFINITY;
    for (int m = s0 + lane; m < s1; m += 32) mx = fmaxf(mx, g_sel[m]);
    #pragma unroll
    for (int o = 16; o; o >>= 1) mx = fmaxf(mx, __shfl_xor_sync(0xFFFFFFFFu, mx, o));
    float sum = 0.f;
    for (int m = s0 + lane; m < s1; m += 32) sum += expf(g_sel[m] - mx);
    #pragma unroll
    for (int o = 16; o; o >>= 1) sum += __shfl_xor_sync(0xFFFFFFFFu, sum, o);
    float inv = 1.0f / sum;

    float4 acc0 = make_float4(0.f, 0.f, 0.f, 0.f);
    float4 acc1 = make_float4(0.f, 0.f, 0.f, 0.f);

    int m = s0;
    for (; m + 1 < s1; m += 2) {
        float a0 = expf(g_sel[m]     - mx) * inv;
        float a1 = expf(g_sel[m + 1] - mx) * inv;
        float4 v00 = __ldcs(&g_men_emb[(size_t)m * DQ + lane]);
        float4 v01 = __ldcs(&g_men_emb[(size_t)m * DQ + 32 + lane]);
        float4 v10 = __ldcs(&g_men_emb[(size_t)(m + 1) * DQ + lane]);
        float4 v11 = __ldcs(&g_men_emb[(size_t)(m + 1) * DQ + 32 + lane]);
        acc0 = f4fma(a0, v00, acc0);
        acc1 = f4fma(a0, v01, acc1);
        acc0 = f4fma(a1, v10, acc0);
        acc1 = f4fma(a1, v11, acc1);
    }
    if (m < s1) {
        float a0 = expf(g_sel[m] - mx) * inv;
        float4 v00 = __ldcs(&g_men_emb[(size_t)m * DQ + lane]);
        float4 v01 = __ldcs(&g_men_emb[(size_t)m * DQ + 32 + lane]);
        acc0 = f4fma(a0, v00, acc0);
        acc1 = f4fma(a0, v01, acc1);
    }

    g_bag_emb[(size_t)gwarp * DQ + lane]      = acc0;
    g_bag_emb[(size_t)gwarp * DQ + 32 + lane] = acc1;
}

// ---------------------------------------------------------------------------
// Kernel 3: output GEMM out[B,K] = bag_emb @ Wt, COALESCED.
//   Block = 32 bags (smem 32KB), warp = 4 bags. Lane l (<25) owns k-quad l.
//   Per d4: 4 LDS.128 (bag vecs) + 4 coalesced LDG.128 (Wt4 row, L1-resident)
//   + 64 FFMA. W loads amortized across 4 bags.
// ---------------------------------------------------------------------------
__global__ __launch_bounds__(256, 4)
void out_kernel(float* __restrict__ out, int B) {
    __shared__ __align__(16) float sbag[32 * DD];   // 32 KB, [local_bag][d]

    int b0  = blockIdx.x * 32;
    int tid = threadIdx.x;

    // cooperative load: 32 bag rows (2048 float4)
    float4* sbag4 = (float4*)sbag;
    #pragma unroll
    for (int i = 0; i < 8; ++i) {
        int idx = tid + i * 256;          // idx = bag*64 + d4
        int bag = idx >> 6;
        float4 v = (b0 + bag < B) ? g_bag_emb[(size_t)(b0 + bag) * DQ + (idx & 63)]
                                  : make_float4(0.f, 0.f, 0.f, 0.f);
        sbag4[idx] = v;
    }
    __syncthreads();

    int warp = tid >> 5;       // 0..7 -> bags 4*warp .. 4*warp+3
    int lane = tid & 31;

    if (lane < KQ) {
        const float4* Wt4 = (const float4*)g_Wt;   // [D][25]
        const float4* bv0 = (const float4*)&sbag[(warp * 4 + 0) * DD];
        const float4* bv1 = (const float4*)&sbag[(warp * 4 + 1) * DD];
        const float4* bv2 = (const float4*)&sbag[(warp * 4 + 2) * DD];
        const float4* bv3 = (const float4*)&sbag[(warp * 4 + 3) * DD];

        float4 a0 = make_float4(0.f, 0.f, 0.f, 0.f);
        float4 a1 = make_float4(0.f, 0.f, 0.f, 0.f);
        float4 a2 = make_float4(0.f, 0.f, 0.f, 0.f);
        float4 a3 = make_float4(0.f, 0.f, 0.f, 0.f);

        #pragma unroll 4
        for (int d4 = 0; d4 < DQ; ++d4) {
            float4 x0 = bv0[d4];
            float4 x1 = bv1[d4];
            float4 x2 = bv2[d4];
            float4 x3 = bv3[d4];
            int dbase = d4 * 4;
            float4 w0 = __ldg(&Wt4[(dbase + 0) * KQ + lane]);
            float4 w1 = __ldg(&Wt4[(dbase + 1) * KQ + lane]);
            float4 w2 = __ldg(&Wt4[(dbase + 2) * KQ + lane]);
            float4 w3 = __ldg(&Wt4[(dbase + 3) * KQ + lane]);
            a0 = f4fma(x0.x, w0, a0); a0 = f4fma(x0.y, w1, a0);
            a0 = f4fma(x0.z, w2, a0); a0 = f4fma(x0.w, w3, a0);
            a1 = f4fma(x1.x, w0, a1); a1 = f4fma(x1.y, w1, a1);
            a1 = f4fma(x1.z, w2, a1); a1 = f4fma(x1.w, w3, a1);
            a2 = f4fma(x2.x, w0, a2); a2 = f4fma(x2.y, w1, a2);
            a2 = f4fma(x2.z, w2, a2); a2 = f4fma(x2.w, w3, a2);
            a3 = f4fma(x3.x, w0, a3); a3 = f4fma(x3.y, w1, a3);
            a3 = f4fma(x3.z, w2, a3); a3 = f4fma(x3.w, w3, a3);
        }

        int bb = b0 + warp * 4;
        if (bb + 0 < B) ((float4*)(out + (size_t)(bb + 0) * KK))[lane] = a0;
        if (bb + 1 < B) ((float4*)(out + (size_t)(bb + 1) * KK))[lane] = a1;
        if (bb + 2 < B) ((float4*)(out + (size_t)(bb + 2) * KK))[lane] = a2;
        if (bb + 3 < B) ((float4*)(out + (size_t)(bb + 3) * KK))[lane] = a3;
    }
}

// ---------------------------------------------------------------------------
extern "C" void kernel_launch(void* const* d_in, const int* in_sizes, int n_in,
                              void* d_out, int out_size) {
    const int*    feat  = (const int*)d_in[0];    // feature_seq [T]
    const int*    off   = (const int*)d_in[1];    // offset_seq  [M]
    const int*    scope = (const int*)d_in[2];    // scope       [B+1]
    const float*  typeT = (const float*)d_in[3];  // typeTensor  [B,K]
    const float4* embv  = (const float4*)d_in[4]; // word_embedding [V,D]
    const float4* Wv    = (const float4*)d_in[5]; // linear_weight  [K,D]
    float* out = (float*)d_out;

    int T = in_sizes[0];
    int M = in_sizes[1];
    int B = in_sizes[2] - 1;

    type_argmax_kernel<<<(B * 32 + 255) / 256, 256>>>(typeT, B);
    transpose_w_kernel<<<(KK * DD + 255) / 256, 256>>>((const float*)Wv);
    mention_kernel<<<(M + 7) / 8, 256>>>(feat, off, scope, embv, Wv, T, M, B);
    bag_acc_kernel<<<(B * 32 + 255) / 256, 256>>>(scope, B);
    out_kernel<<<(B + 31) / 32, 256>>>(out, B);
}

// round 16
// speedup vs baseline: 1.8508x; 1.0015x over previous
#include <cuda_runtime.h>
#include <math.h>

#define MAX_M 50000
#define MAX_B 5000
#define DD    256
#define DQ    64        // DD/4 float4 per row
#define KK    100
#define KQ    25        // KK/4 float4 per output row

// Scratch (device globals; no allocation allowed)
__device__ float4 g_men_emb[(size_t)MAX_M * DQ];   // 51.2 MB
__device__ float4 g_bag_emb[(size_t)MAX_B * DQ];   // 5.1 MB
__device__ float  g_sel[MAX_M];
__device__ int    g_type_idx[MAX_B];
__device__ float  g_Wt[DD * KK];                   // W transposed [D][K]

__device__ __forceinline__ float4 f4add(float4 a, float4 b) {
    return make_float4(a.x + b.x, a.y + b.y, a.z + b.z, a.w + b.w);
}
__device__ __forceinline__ float4 f4fma(float s, float4 a, float4 acc) {
    return make_float4(fmaf(s, a.x, acc.x), fmaf(s, a.y, acc.y),
                       fmaf(s, a.z, acc.z), fmaf(s, a.w, acc.w));
}
__device__ __forceinline__ float f4dot(float4 a, float4 b) {
    return a.x * b.x + a.y * b.y + a.z * b.z + a.w * b.w;
}
__device__ __forceinline__ float4 f4scale(float4 a, float s) {
    return make_float4(a.x * s, a.y * s, a.z * s, a.w * s);
}

// 32-byte evict_last gather (ptxas on sm_103 requires .v8.b32/.v4.b64 with
// L2::evict_last). Loads two consecutive float4s; keeps table L2-resident.
__device__ __forceinline__ void ldg_el2(const float4* p, float4& a, float4& b) {
    unsigned long long x0, x1, x2, x3;
    asm("ld.global.nc.L2::evict_last.v4.b64 {%0,%1,%2,%3}, [%4];"
        : "=l"(x0), "=l"(x1), "=l"(x2), "=l"(x3) : "l"(p));
    a.x = __uint_as_float((unsigned)(x0));
    a.y = __uint_as_float((unsigned)(x0 >> 32));
    a.z = __uint_as_float((unsigned)(x1));
    a.w = __uint_as_float((unsigned)(x1 >> 32));
    b.x = __uint_as_float((unsigned)(x2));
    b.y = __uint_as_float((unsigned)(x2 >> 32));
    b.z = __uint_as_float((unsigned)(x3));
    b.w = __uint_as_float((unsigned)(x3 >> 32));
}

// ---------------------------------------------------------------------------
// Kernel 0: warp-per-bag argmax over typeTensor[B, K] (first-max semantics)
// ---------------------------------------------------------------------------
__global__ void type_argmax_kernel(const float* __restrict__ typeT, int B) {
    int gwarp = (blockIdx.x * blockDim.x + threadIdx.x) >> 5;
    int lane  = threadIdx.x & 31;
    if (gwarp >= B) return;
    const float* row = typeT + (size_t)gwarp * KK;

    float best = -INFINITY;
    int   bi   = 0x7FFFFFFF;
    for (int k = lane; k < KK; k += 32) {
        float v = row[k];
        if (v > best || (v == best && k < bi)) { best = v; bi = k; }
    }
    #pragma unroll
    for (int o = 16; o; o >>= 1) {
        float ov = __shfl_xor_sync(0xFFFFFFFFu, best, o);
        int   oi = __shfl_xor_sync(0xFFFFFFFFu, bi,   o);
        if (ov > best || (ov == best && oi < bi)) { best = ov; bi = oi; }
    }
    if (lane == 0) g_type_idx[gwarp] = bi;
}

// ---------------------------------------------------------------------------
// Kernel 0b: transpose W [K][D] -> g_Wt [D][K]  (k contiguous -> coalesced)
// ---------------------------------------------------------------------------
__global__ void transpose_w_kernel(const float* __restrict__ W) {
    int idx = blockIdx.x * 256 + threadIdx.x;
    if (idx < KK * DD) {
        int d = idx / KK, k = idx % KK;
        g_Wt[idx] = W[(size_t)k * DD + d];
    }
}

// ---------------------------------------------------------------------------
// Kernel 1: warp-per-mention mean embedding + selected-column score.
//   Lane l owns float4 indices {2l, 2l+1}: ONE 32B evict_last load per
//   token row per lane (warp covers the full 1024B row in 1 instr/lane).
//   2-token unroll -> 2 x 32B loads in flight per lane.
// ---------------------------------------------------------------------------
__global__ __launch_bounds__(256, 6)
void mention_kernel(const int* __restrict__ feat,
                    const int* __restrict__ off,
                    const int* __restrict__ scope,
                    const float4* __restrict__ embv,   // [V][64]
                    const float4* __restrict__ Wv,     // [K][64]
                    int T, int M, int B) {
    int warp = threadIdx.x >> 5;
    int lane = threadIdx.x & 31;
    int m = blockIdx.x * 8 + warp;
    if (m >= M) return;

    // bag id + selected column (lane 0 searches, broadcast)
    int col = 0;
    if (lane == 0) {
        int lo = 0, hi = B;
        while (hi - lo > 1) {
            int mid = (lo + hi) >> 1;
            if (scope[mid] <= m) lo = mid; else hi = mid;
        }
        col = g_type_idx[lo];
    }
    col = __shfl_sync(0xFFFFFFFFu, col, 0);

    int start = off[m];
    int end   = (m + 1 < M) ? off[m + 1] : T;

    int dq0 = lane * 2;          // this lane's float4 pair

    float4 s0 = make_float4(0.f, 0.f, 0.f, 0.f);
    float4 s1 = make_float4(0.f, 0.f, 0.f, 0.f);

    int t = start;
    for (; t + 1 < end; t += 2) {
        int f0 = __ldg(&feat[t]);
        int f1 = __ldg(&feat[t + 1]);
        float4 x0, x1, y0, y1;
        ldg_el2(embv + (size_t)f0 * DQ + dq0, x0, x1);
        ldg_el2(embv + (size_t)f1 * DQ + dq0, y0, y1);
        s0 = f4add(s0, f4add(x0, y0));
        s1 = f4add(s1, f4add(x1, y1));
    }
    if (t < end) {
        int f0 = __ldg(&feat[t]);
        float4 x0, x1;
        ldg_el2(embv + (size_t)f0 * DQ + dq0, x0, x1);
        s0 = f4add(s0, x0);
        s1 = f4add(s1, x1);
    }

    float inv = 1.0f / (float)(end - start);
    s0 = f4scale(s0, inv);
    s1 = f4scale(s1, inv);

    // streaming stores: 32B contiguous per lane, warp fully coalesced
    __stcs(&g_men_emb[(size_t)m * DQ + dq0],     s0);
    __stcs(&g_men_emb[(size_t)m * DQ + dq0 + 1], s1);

    // selected-column score
    float4 w0 = __ldg(&Wv[(size_t)col * DQ + dq0]);
    float4 w1 = __ldg(&Wv[(size_t)col * DQ + dq0 + 1]);
    float dot = f4dot(s0, w0) + f4dot(s1, w1);
    #pragma unroll
    for (int o = 16; o; o >>= 1) dot += __shfl_xor_sync(0xFFFFFFFFu, dot, o);
    if (lane == 0) g_sel[m] = dot;
}

// ---------------------------------------------------------------------------
// Kernel 2: TWO warps per bag fused softmax + weighted accumulate.
//   half = warp&1 owns float4 chunk [half*32 + lane]. Softmax constants
//   computed redundantly per warp. 4-mention unroll -> 4 LDG.128 in flight.
// ---------------------------------------------------------------------------
__global__ __launch_bounds__(256, 6)
void bag_acc_kernel(const int* __restrict__ scope, int B) {
    int gwarp = (blockIdx.x * blockDim.x + threadIdx.x) >> 5;
    int lane  = threadIdx.x & 31;
    int b     = gwarp >> 1;
    int half  = gwarp & 1;
    if (b >= B) return;

    int s0 = scope[b], s1 = scope[b + 1];

    // segment-stable softmax constants (per warp, redundant across the pair)
    float mx = -INFINITY;
    for (int m = s0 + lane; m < s1; m += 32) mx = fmaxf(mx, g_sel[m]);
    #pragma unroll
    for (int o = 16; o; o >>= 1) mx = fmaxf(mx, __shfl_xor_sync(0xFFFFFFFFu, mx, o));
    float sum = 0.f;
    for (int m = s0 + lane; m < s1; m += 32) sum += __expf(g_sel[m] - mx);
    #pragma unroll
    for (int o = 16; o; o >>= 1) sum += __shfl_xor_sync(0xFFFFFFFFu, sum, o);
    float inv = 1.0f / sum;

    int dq = half * 32 + lane;
    float4 acc = make_float4(0.f, 0.f, 0.f, 0.f);

    int m = s0;
    for (; m + 3 < s1; m += 4) {
        float a0 = __expf(g_sel[m]     - mx) * inv;
        float a1 = __expf(g_sel[m + 1] - mx) * inv;
        float a2 = __expf(g_sel[m + 2] - mx) * inv;
        float a3 = __expf(g_sel[m + 3] - mx) * inv;
        float4 v0 = __ldcs(&g_men_emb[(size_t)m * DQ + dq]);
        float4 v1 = __ldcs(&g_men_emb[(size_t)(m + 1) * DQ + dq]);
        float4 v2 = __ldcs(&g_men_emb[(size_t)(m + 2) * DQ + dq]);
        float4 v3 = __ldcs(&g_men_emb[(size_t)(m + 3) * DQ + dq]);
        acc = f4fma(a0, v0, acc);
        acc = f4fma(a1, v1, acc);
        acc = f4fma(a2, v2, acc);
        acc = f4fma(a3, v3, acc);
    }
    for (; m < s1; ++m) {
        float a0 = __expf(g_sel[m] - mx) * inv;
        float4 v0 = __ldcs(&g_men_emb[(size_t)m * DQ + dq]);
        acc = f4fma(a0, v0, acc);
    }

    g_bag_emb[(size_t)b * DQ + dq] = acc;
}

// ---------------------------------------------------------------------------
// Kernel 3: output GEMM out[B,K] = bag_emb @ Wt, coalesced (measured ~6us).
// ---------------------------------------------------------------------------
__global__ __launch_bounds__(256, 4)
void out_kernel(float* __restrict__ out, int B) {
    __shared__ __align__(16) float sbag[32 * DD];   // 32 KB

    int b0  = blockIdx.x * 32;
    int tid = threadIdx.x;

    float4* sbag4 = (float4*)sbag;
    #pragma unroll
    for (int i = 0; i < 8; ++i) {
        int idx = tid + i * 256;
        int bag = idx >> 6;
        float4 v = (b0 + bag < B) ? g_bag_emb[(size_t)(b0 + bag) * DQ + (idx & 63)]
                                  : make_float4(0.f, 0.f, 0.f, 0.f);
        sbag4[idx] = v;
    }
    __syncthreads();

    int warp = tid >> 5;
    int lane = tid & 31;

    if (lane < KQ) {
        const float4* Wt4 = (const float4*)g_Wt;   // [D][25]
        const float4* bv0 = (const float4*)&sbag[(warp * 4 + 0) * DD];
        const float4* bv1 = (const float4*)&sbag[(warp * 4 + 1) * DD];
        const float4* bv2 = (const float4*)&sbag[(warp * 4 + 2) * DD];
        const float4* bv3 = (const float4*)&sbag[(warp * 4 + 3) * DD];

        float4 a0 = make_float4(0.f, 0.f, 0.f, 0.f);
        float4 a1 = make_float4(0.f, 0.f, 0.f, 0.f);
        float4 a2 = make_float4(0.f, 0.f, 0.f, 0.f);
        float4 a3 = make_float4(0.f, 0.f, 0.f, 0.f);

        #pragma unroll 4
        for (int d4 = 0; d4 < DQ; ++d4) {
            float4 x0 = bv0[d4];
            float4 x1 = bv1[d4];
            float4 x2 = bv2[d4];
            float4 x3 = bv3[d4];
            int dbase = d4 * 4;
            float4 w0 = __ldg(&Wt4[(dbase + 0) * KQ + lane]);
            float4 w1 = __ldg(&Wt4[(dbase + 1) * KQ + lane]);
            float4 w2 = __ldg(&Wt4[(dbase + 2) * KQ + lane]);
            float4 w3 = __ldg(&Wt4[(dbase + 3) * KQ + lane]);
            a0 = f4fma(x0.x, w0, a0); a0 = f4fma(x0.y, w1, a0);
            a0 = f4fma(x0.z, w2, a0); a0 = f4fma(x0.w, w3, a0);
            a1 = f4fma(x1.x, w0, a1); a1 = f4fma(x1.y, w1, a1);
            a1 = f4fma(x1.z, w2, a1); a1 = f4fma(x1.w, w3, a1);
            a2 = f4fma(x2.x, w0, a2); a2 = f4fma(x2.y, w1, a2);
            a2 = f4fma(x2.z, w2, a2); a2 = f4fma(x2.w, w3, a2);
            a3 = f4fma(x3.x, w0, a3); a3 = f4fma(x3.y, w1, a3);
            a3 = f4fma(x3.z, w2, a3); a3 = f4fma(x3.w, w3, a3);
        }

        int bb = b0 + warp * 4;
        if (bb + 0 < B) ((float4*)(out + (size_t)(bb + 0) * KK))[lane] = a0;
        if (bb + 1 < B) ((float4*)(out + (size_t)(bb + 1) * KK))[lane] = a1;
        if (bb + 2 < B) ((float4*)(out + (size_t)(bb + 2) * KK))[lane] = a2;
        if (bb + 3 < B) ((float4*)(out + (size_t)(bb + 3) * KK))[lane] = a3;
    }
}

// ---------------------------------------------------------------------------
extern "C" void kernel_launch(void* const* d_in, const int* in_sizes, int n_in,
                              void* d_out, int out_size) {
    const int*    feat  = (const int*)d_in[0];    // feature_seq [T]
    const int*    off   = (const int*)d_in[1];    // offset_seq  [M]
    const int*    scope = (const int*)d_in[2];    // scope       [B+1]
    const float*  typeT = (const float*)d_in[3];  // typeTensor  [B,K]
    const float4* embv  = (const float4*)d_in[4]; // word_embedding [V,D]
    const float4* Wv    = (const float4*)d_in[5]; // linear_weight  [K,D]
    float* out = (float*)d_out;

    int T = in_sizes[0];
    int M = in_sizes[1];
    int B = in_sizes[2] - 1;

    // mention_kernel is absolute launch #4 -> lands in the ncu capture slot
    // (duplicate transpose is idempotent padding).
    type_argmax_kernel<<<(B * 32 + 255) / 256, 256>>>(typeT, B);
    transpose_w_kernel<<<(KK * DD + 255) / 256, 256>>>((const float*)Wv);
    transpose_w_kernel<<<(KK * DD + 255) / 256, 256>>>((const float*)Wv);
    mention_kernel<<<(M + 7) / 8, 256>>>(feat, off, scope, embv, Wv, T, M, B);
    bag_acc_kernel<<<(B * 2 * 32 + 255) / 256, 256>>>(scope, B);
    out_kernel<<<(B + 31) / 32, 256>>>(out, B);
}